// round 4
// baseline (speedup 1.0000x reference)
#include <cuda_runtime.h>

#define BN 4
#define SEQ 1024
#define DIMQ 1024
#define KVD 2048
#define NH 16
#define HD 64
#define LN_EPS 1e-5f

// Scratch (allocation-free rule: device globals)
__device__ float g_q[(size_t)BN * SEQ * DIMQ];          // [b*N + i][DIMQ]   = x @ Wq
__device__ float g_kv[(size_t)BN * SEQ * KVD];          // [b*M + j][2048]   = context @ Wkv (k | v)
__device__ float g_s[(size_t)BN * SEQ * NH * SEQ];      // [b][i][h][j] softmax probs (256 MB)

// ---------------------------------------------------------------------------
// Generic fp32 GEMM: C[Mr,Nc] = A[Mr,K] @ W[K,Nc], row-major, dims multiple of 128/8.
// Block 128x128, K-tile 8, 256 threads, 8x8 register tile.
// ---------------------------------------------------------------------------
__global__ __launch_bounds__(256) void gemm_kernel(
    const float* __restrict__ A, const float* __restrict__ W, float* __restrict__ C,
    int Mr, int Nc, int K)
{
    __shared__ float As[8][128];
    __shared__ float Ws[8][128];
    int t = threadIdx.x;
    int m0 = blockIdx.y * 128, n0 = blockIdx.x * 128;
    int ty = t >> 4, tx = t & 15;
    int ar = t >> 1, ah = (t & 1) * 4;      // A loader: row ar, k-quad ah
    int wr = t >> 5, wc = (t & 31) * 4;     // W loader: k-row wr, col-quad wc

    float acc[8][8];
#pragma unroll
    for (int u = 0; u < 8; u++)
#pragma unroll
        for (int v = 0; v < 8; v++) acc[u][v] = 0.f;

    for (int k0 = 0; k0 < K; k0 += 8) {
        float4 av = *(const float4*)(A + (size_t)(m0 + ar) * K + k0 + ah);
        float4 wv = *(const float4*)(W + (size_t)(k0 + wr) * Nc + n0 + wc);
        As[ah + 0][ar] = av.x; As[ah + 1][ar] = av.y;
        As[ah + 2][ar] = av.z; As[ah + 3][ar] = av.w;
        *(float4*)&Ws[wr][wc] = wv;
        __syncthreads();
#pragma unroll
        for (int kk = 0; kk < 8; kk++) {
            float4 a0 = *(const float4*)&As[kk][ty * 8];
            float4 a1 = *(const float4*)&As[kk][ty * 8 + 4];
            float4 b0 = *(const float4*)&Ws[kk][tx * 8];
            float4 b1 = *(const float4*)&Ws[kk][tx * 8 + 4];
            float a[8] = {a0.x, a0.y, a0.z, a0.w, a1.x, a1.y, a1.z, a1.w};
            float b[8] = {b0.x, b0.y, b0.z, b0.w, b1.x, b1.y, b1.z, b1.w};
#pragma unroll
            for (int u = 0; u < 8; u++)
#pragma unroll
                for (int v = 0; v < 8; v++)
                    acc[u][v] = fmaf(a[u], b[v], acc[u][v]);
        }
        __syncthreads();
    }
#pragma unroll
    for (int u = 0; u < 8; u++) {
        float* cp = C + (size_t)(m0 + ty * 8 + u) * Nc + n0 + tx * 8;
        *(float4*)cp       = make_float4(acc[u][0], acc[u][1], acc[u][2], acc[u][3]);
        *(float4*)(cp + 4) = make_float4(acc[u][4], acc[u][5], acc[u][6], acc[u][7]);
    }
}

// ---------------------------------------------------------------------------
// Scores + softmax. CTA = (i-tile of 32 rows, head h, batch b).
// Keeps the full 32x1024 score tile in smem, then warp-per-row softmax,
// writes probs to g_s layout [b][i][h][j] (contiguous over j).
// ---------------------------------------------------------------------------
__global__ __launch_bounds__(256) void scores_kernel(
    const float* __restrict__ q, const float* __restrict__ kv, float* __restrict__ s)
{
    extern __shared__ float sm[];
    float* sc = sm;                        // [32][1025]
    float* qs = sc + 32 * 1025;            // [32][65]
    float* ks = qs + 32 * 65;              // [64][132]  (ks[d][j], padded, f4-aligned)

    int t = threadIdx.x;
    int i0 = blockIdx.x * 32;
    int h  = blockIdx.y;
    int b  = blockIdx.z;
    const float scale = 0.125f;            // 64^-0.5

    // load q tile rows i0..i0+31, cols h*64..+63
    for (int idx = t; idx < 32 * 64; idx += 256) {
        int r = idx >> 6, d = idx & 63;
        qs[r * 65 + d] = q[(size_t)(b * SEQ + i0 + r) * DIMQ + h * HD + d];
    }

    int ty = t >> 5, tx = t & 31;          // 8x32 threads -> 4x4 tile each over 32x128
    for (int j0 = 0; j0 < SEQ; j0 += 128) {
        for (int idx = t; idx < 128 * 64; idx += 256) {
            int jj = idx >> 6, d = idx & 63;
            ks[d * 132 + jj] = kv[(size_t)(b * SEQ + j0 + jj) * KVD + h * HD + d];
        }
        __syncthreads();
        float acc[4][4];
#pragma unroll
        for (int u = 0; u < 4; u++)
#pragma unroll
            for (int v = 0; v < 4; v++) acc[u][v] = 0.f;
#pragma unroll 8
        for (int kk = 0; kk < 64; kk++) {
            float a[4];
#pragma unroll
            for (int u = 0; u < 4; u++) a[u] = qs[(ty * 4 + u) * 65 + kk];
            float4 bv = *(const float4*)&ks[kk * 132 + tx * 4];
            float bb[4] = {bv.x, bv.y, bv.z, bv.w};
#pragma unroll
            for (int u = 0; u < 4; u++)
#pragma unroll
                for (int v = 0; v < 4; v++)
                    acc[u][v] = fmaf(a[u], bb[v], acc[u][v]);
        }
#pragma unroll
        for (int u = 0; u < 4; u++)
#pragma unroll
            for (int v = 0; v < 4; v++)
                sc[(ty * 4 + u) * 1025 + j0 + tx * 4 + v] = acc[u][v];
        __syncthreads();
    }

    // softmax: 8 warps, 4 rows each
    int wid = t >> 5, lane = t & 31;
#pragma unroll
    for (int rr = 0; rr < 4; rr++) {
        int r = wid * 4 + rr;
        float mx = -1e30f;
        for (int jj = lane; jj < SEQ; jj += 32) mx = fmaxf(mx, sc[r * 1025 + jj]);
#pragma unroll
        for (int o = 16; o > 0; o >>= 1) mx = fmaxf(mx, __shfl_xor_sync(0xffffffffu, mx, o));
        float sum = 0.f;
        for (int jj = lane; jj < SEQ; jj += 32) {
            float e = __expf(scale * (sc[r * 1025 + jj] - mx));
            sc[r * 1025 + jj] = e;
            sum += e;
        }
#pragma unroll
        for (int o = 16; o > 0; o >>= 1) sum += __shfl_xor_sync(0xffffffffu, sum, o);
        float inv = 1.f / sum;
        size_t base = ((size_t)(b * SEQ + i0 + r) * NH + h) * SEQ;
        for (int jj = lane; jj < SEQ; jj += 32) s[base + jj] = sc[r * 1025 + jj] * inv;
    }
}

// ---------------------------------------------------------------------------
// Talking-heads mix + LayerNorm + AV. CTA = (16-row i-tile, batch), all 16 heads.
// Per 16-wide j-tile: gather 16 heads of s per (i,j), 16x16 mix + LN in smem,
// then register-tiled accumulate (4 rows x 16 cols per thread) vs smem v-tile.
// ---------------------------------------------------------------------------
__global__ __launch_bounds__(256, 2) void av_kernel(
    const float* __restrict__ s, const float* __restrict__ kv,
    const float* __restrict__ Wt, const float* __restrict__ gamma,
    const float* __restrict__ beta, float* __restrict__ out)
{
    extern __shared__ float sm[];
    float* vs  = sm;                        // [16][1028] v tile
    float* w2  = vs + 16 * 1028;            // [16][16][17] mixed+LN weights [i][g][j]
    float* wts = w2 + 16 * 16 * 17;         // [16][17]
    float* gm  = wts + 16 * 17;             // [16]
    float* bt  = gm + 16;                   // [16]

    int t  = threadIdx.x;
    int i0 = blockIdx.x * 16;
    int b  = blockIdx.y;
    int rg  = t >> 6;                       // row group 0..3 (rows rg*4..+3)
    int rem = t & 63;
    int h   = rem >> 2;                     // head 0..15
    int dg  = rem & 3;                      // 16-col group within head
    int il  = t >> 4, jl = t & 15;          // mix-phase pair (i_local, j_local)

    wts[(t >> 4) * 17 + (t & 15)] = Wt[t];
    if (t < 16) { gm[t] = gamma[t]; bt[t] = beta[t]; }

    float acc[4][16];
#pragma unroll
    for (int u = 0; u < 4; u++)
#pragma unroll
        for (int e = 0; e < 16; e++) acc[u][e] = 0.f;

    for (int j0 = 0; j0 < SEQ; j0 += 16) {
        __syncthreads();   // protects vs/w2 reuse and (first iter) wts/gm/bt
        // load v tile: 16 rows x 1024 cols
        for (int idx = t; idx < 16 * 256; idx += 256) {
            int jj = idx >> 8, c4 = idx & 255;
            float4 vv = *(const float4*)(kv + (size_t)(b * SEQ + j0 + jj) * KVD + DIMQ + c4 * 4);
            *(float4*)&vs[jj * 1028 + c4 * 4] = vv;
        }
        // mix + LN for pair (il, j0+jl)
        {
            float sv[16];
            size_t sb = (size_t)(b * SEQ + i0 + il) * NH * SEQ + j0 + jl;
#pragma unroll
            for (int h2 = 0; h2 < 16; h2++) sv[h2] = s[sb + (size_t)h2 * SEQ];
            float m_[16];
            float mu = 0.f;
#pragma unroll
            for (int g = 0; g < 16; g++) {
                float m = 0.f;
#pragma unroll
                for (int h2 = 0; h2 < 16; h2++) m = fmaf(sv[h2], wts[h2 * 17 + g], m);
                m_[g] = m;
                mu += m;
            }
            mu *= (1.f / 16.f);
            float var = 0.f;
#pragma unroll
            for (int g = 0; g < 16; g++) { float d = m_[g] - mu; var = fmaf(d, d, var); }
            var *= (1.f / 16.f);
            float ivr = rsqrtf(var + LN_EPS);
#pragma unroll
            for (int g = 0; g < 16; g++)
                w2[(il * 16 + g) * 17 + jl] = (m_[g] - mu) * ivr * gm[g] + bt[g];
        }
        __syncthreads();
        // accumulate
#pragma unroll
        for (int jj = 0; jj < 16; jj++) {
            float w[4];
#pragma unroll
            for (int u = 0; u < 4; u++)
                w[u] = w2[((rg * 4 + u) * 16 + h) * 17 + jj];
            const float* vp = &vs[jj * 1028 + h * HD + dg * 16];
            float4 v0 = *(const float4*)(vp);
            float4 v1 = *(const float4*)(vp + 4);
            float4 v2 = *(const float4*)(vp + 8);
            float4 v3 = *(const float4*)(vp + 12);
            float vv[16] = {v0.x, v0.y, v0.z, v0.w, v1.x, v1.y, v1.z, v1.w,
                            v2.x, v2.y, v2.z, v2.w, v3.x, v3.y, v3.z, v3.w};
#pragma unroll
            for (int u = 0; u < 4; u++)
#pragma unroll
                for (int e = 0; e < 16; e++)
                    acc[u][e] = fmaf(w[u], vv[e], acc[u][e]);
        }
    }
    // epilogue
#pragma unroll
    for (int u = 0; u < 4; u++) {
        float* op = out + (size_t)(b * SEQ + i0 + rg * 4 + u) * DIMQ + h * HD + dg * 16;
        *(float4*)(op)      = make_float4(acc[u][0],  acc[u][1],  acc[u][2],  acc[u][3]);
        *(float4*)(op + 4)  = make_float4(acc[u][4],  acc[u][5],  acc[u][6],  acc[u][7]);
        *(float4*)(op + 8)  = make_float4(acc[u][8],  acc[u][9],  acc[u][10], acc[u][11]);
        *(float4*)(op + 12) = make_float4(acc[u][12], acc[u][13], acc[u][14], acc[u][15]);
    }
}

extern "C" void kernel_launch(void* const* d_in, const int* in_sizes, int n_in,
                              void* d_out, int out_size)
{
    const float* x     = (const float*)d_in[0];
    const float* ctx   = (const float*)d_in[1];
    const float* Wq    = (const float*)d_in[2];
    const float* Wkv   = (const float*)d_in[3];
    const float* Wt    = (const float*)d_in[4];
    const float* gamma = (const float*)d_in[5];
    const float* beta  = (const float*)d_in[6];
    float* out = (float*)d_out;

    float *qp, *kvp, *sp;
    cudaGetSymbolAddress((void**)&qp, g_q);
    cudaGetSymbolAddress((void**)&kvp, g_kv);
    cudaGetSymbolAddress((void**)&sp, g_s);

    // projections
    gemm_kernel<<<dim3(DIMQ / 128, BN * SEQ / 128), 256>>>(x, Wq, qp, BN * SEQ, DIMQ, DIMQ);
    gemm_kernel<<<dim3(KVD / 128, BN * SEQ / 128), 256>>>(ctx, Wkv, kvp, BN * SEQ, KVD, DIMQ);

    // scores + softmax
    int smem_sc = (32 * 1025 + 32 * 65 + 64 * 132) * 4;
    cudaFuncSetAttribute(scores_kernel, cudaFuncAttributeMaxDynamicSharedMemorySize, smem_sc);
    scores_kernel<<<dim3(SEQ / 32, NH, BN), 256, smem_sc>>>(qp, kvp, sp);

    // talking heads + LN + AV
    int smem_av = (16 * 1028 + 16 * 16 * 17 + 16 * 17 + 32) * 4;
    cudaFuncSetAttribute(av_kernel, cudaFuncAttributeMaxDynamicSharedMemorySize, smem_av);
    av_kernel<<<dim3(SEQ / 16, BN), 256, smem_av>>>(sp, kvp, Wt, gamma, beta, out);
}

// round 10
// speedup vs baseline: 2.5393x; 2.5393x over previous
#include <cuda_runtime.h>
#include <cuda_bf16.h>

using bf16 = __nv_bfloat16;
using bf162 = __nv_bfloat162;

#define SEQ 1024
#define NB 4
#define NH 16
#define HD 64
#define LN_EPS 1e-5f

// ---------------- scratch (device globals; no allocations allowed) ----------
__device__ bf16 g_xhi[4194304],  g_xlo[4194304];     // x split
__device__ bf16 g_chi[4194304],  g_clo[4194304];     // context split
__device__ bf16 g_wqThi[1048576], g_wqTlo[1048576];  // Wq^T  [n][k]
__device__ bf16 g_wkThi[2097152], g_wkTlo[2097152];  // Wkv^T [n][k]
__device__ float g_q[4194304];                        // x@Wq fp32
__device__ float g_kv[8388608];                       // ctx@Wkv fp32 (k|v)
__device__ bf16 g_qhi[4194304],  g_qlo[4194304];
__device__ bf16 g_kvhi[8388608], g_kvlo[8388608];
__device__ bf16 g_vThi[4194304], g_vTlo[4194304];    // v^T per batch [d][j]
__device__ float g_s[67108864];                       // scores -> probs [b][i][h][j]
__device__ bf16 g_whi[67108864], g_wlo[67108864];    // mixed+LN weights [b,g][i][j]

// ---------------- split fp32 -> bf16 hi/lo ----------------------------------
__global__ __launch_bounds__(256) void split_kernel(
    const float* __restrict__ in, bf16* __restrict__ hi, bf16* __restrict__ lo, int n)
{
    int i = (blockIdx.x * 256 + threadIdx.x) * 4;
    if (i >= n) return;
    float4 v = *(const float4*)(in + i);
    bf16 h0 = __float2bfloat16(v.x), h1 = __float2bfloat16(v.y);
    bf16 h2 = __float2bfloat16(v.z), h3 = __float2bfloat16(v.w);
    bf16 l0 = __float2bfloat16(v.x - __bfloat162float(h0));
    bf16 l1 = __float2bfloat16(v.y - __bfloat162float(h1));
    bf16 l2 = __float2bfloat16(v.z - __bfloat162float(h2));
    bf16 l3 = __float2bfloat16(v.w - __bfloat162float(h3));
    bf162 p;
    p.x = h0; p.y = h1; *(bf162*)(hi + i)     = p;
    p.x = h2; p.y = h3; *(bf162*)(hi + i + 2) = p;
    p.x = l0; p.y = l1; *(bf162*)(lo + i)     = p;
    p.x = l2; p.y = l3; *(bf162*)(lo + i + 2) = p;
}

// ---------------- transpose + split: out[c][r] = in[r][c] -------------------
__global__ __launch_bounds__(256) void tsplit_kernel(
    const float* __restrict__ in, long inZ, int inStride,
    bf16* __restrict__ hi, bf16* __restrict__ lo, long outZ, int outStride)
{
    __shared__ float tile[32][33];
    const float* ip = in + (long)blockIdx.z * inZ;
    int r0 = blockIdx.y * 32, c0 = blockIdx.x * 32;
    int t = threadIdx.x;
    {
        int r = t >> 3, c4 = (t & 7) * 4;
        float4 v = *(const float4*)(ip + (long)(r0 + r) * inStride + c0 + c4);
        tile[r][c4] = v.x; tile[r][c4 + 1] = v.y; tile[r][c4 + 2] = v.z; tile[r][c4 + 3] = v.w;
    }
    __syncthreads();
    int c = t >> 3, r4 = (t & 7) * 4;
    long ob = (long)blockIdx.z * outZ + (long)(c0 + c) * outStride + r0 + r4;
    float f0 = tile[r4][c], f1 = tile[r4 + 1][c], f2 = tile[r4 + 2][c], f3 = tile[r4 + 3][c];
    bf16 h0 = __float2bfloat16(f0), h1 = __float2bfloat16(f1);
    bf16 h2 = __float2bfloat16(f2), h3 = __float2bfloat16(f3);
    bf162 p;
    p.x = h0; p.y = h1; *(bf162*)(hi + ob)     = p;
    p.x = h2; p.y = h3; *(bf162*)(hi + ob + 2) = p;
    p.x = __float2bfloat16(f0 - __bfloat162float(h0));
    p.y = __float2bfloat16(f1 - __bfloat162float(h1));
    *(bf162*)(lo + ob) = p;
    p.x = __float2bfloat16(f2 - __bfloat162float(h2));
    p.y = __float2bfloat16(f3 - __bfloat162float(h3));
    *(bf162*)(lo + ob + 2) = p;
}

// ---------------- mma.sync helper -------------------------------------------
__device__ __forceinline__ void mma16816(float* d, const unsigned* a, unsigned b0, unsigned b1)
{
    asm volatile(
        "mma.sync.aligned.m16n8k16.row.col.f32.bf16.bf16.f32 "
        "{%0,%1,%2,%3}, {%4,%5,%6,%7}, {%8,%9}, {%0,%1,%2,%3};\n"
        : "+f"(d[0]), "+f"(d[1]), "+f"(d[2]), "+f"(d[3])
        : "r"(a[0]), "r"(a[1]), "r"(a[2]), "r"(a[3]), "r"(b0), "r"(b1));
}

// ---------------- split-bf16 GEMM: C[m][n] = sum_k A[m][k] * B[n][k] --------
// A,B given as hi/lo bf16. 3-term: Ahi*Bhi + Ahi*Blo + Alo*Bhi (fp32 accum).
// Batched: z -> (zb = z/HB, zr = z%HB) with per-operand strides.
template <int BM, int BNt, int WM, int WNt>
__global__ __launch_bounds__(256) void gemm_bf16(
    const bf16* __restrict__ Ahi, const bf16* __restrict__ Alo,
    const bf16* __restrict__ Bhi, const bf16* __restrict__ Blo,
    float* __restrict__ C, int K, int lda, int ldb, int ldc,
    int HB, long sA1, long sA2, long sB1, long sB2, long sC1, long sC2)
{
    constexpr int KS = 40;                 // smem stride (bf16 units), conflict-free
    __shared__ bf16 As[2][BM * KS];
    __shared__ bf16 Bs[2][BNt * KS];

    int z = blockIdx.z;
    long zb = z / HB, zr = z % HB;
    const bf16* Ah = Ahi + zb * sA1 + zr * sA2 + (long)(blockIdx.y * BM) * lda;
    const bf16* Al = Alo + zb * sA1 + zr * sA2 + (long)(blockIdx.y * BM) * lda;
    const bf16* Bh = Bhi + zb * sB1 + zr * sB2 + (long)(blockIdx.x * BNt) * ldb;
    const bf16* Bl = Blo + zb * sB1 + zr * sB2 + (long)(blockIdx.x * BNt) * ldb;
    float* Cp = C + zb * sC1 + zr * sC2 + (long)(blockIdx.y * BM) * ldc + blockIdx.x * BNt;

    int t = threadIdx.x, w = t >> 5, lane = t & 31;
    constexpr int MW = BM / WM;
    constexpr int MB = WM / 16, NBk = WNt / 8;
    int mw = (w % MW) * WM, nw = (w / MW) * WNt;
    int fr = lane >> 2, fc = (lane & 3) * 2;

    float acc[MB][NBk][4];
#pragma unroll
    for (int i = 0; i < MB; i++)
#pragma unroll
        for (int j = 0; j < NBk; j++)
#pragma unroll
            for (int e = 0; e < 4; e++) acc[i][j][e] = 0.f;

    for (int k0 = 0; k0 < K; k0 += 32) {
        __syncthreads();
#pragma unroll 2
        for (int i = t; i < BM * 4; i += 256) {
            int m = i >> 2, kv = (i & 3) * 8;
            *(uint4*)&As[0][m * KS + kv] = *(const uint4*)(Ah + (long)m * lda + k0 + kv);
            *(uint4*)&As[1][m * KS + kv] = *(const uint4*)(Al + (long)m * lda + k0 + kv);
        }
#pragma unroll 2
        for (int i = t; i < BNt * 4; i += 256) {
            int n = i >> 2, kv = (i & 3) * 8;
            *(uint4*)&Bs[0][n * KS + kv] = *(const uint4*)(Bh + (long)n * ldb + k0 + kv);
            *(uint4*)&Bs[1][n * KS + kv] = *(const uint4*)(Bl + (long)n * ldb + k0 + kv);
        }
        __syncthreads();
#pragma unroll
        for (int ks = 0; ks < 32; ks += 16) {
            unsigned ah[MB][4], al[MB][4];
#pragma unroll
            for (int mb = 0; mb < MB; mb++) {
                int mbase = mw + mb * 16;
                ah[mb][0] = *(unsigned*)&As[0][(mbase + fr) * KS + ks + fc];
                ah[mb][1] = *(unsigned*)&As[0][(mbase + fr + 8) * KS + ks + fc];
                ah[mb][2] = *(unsigned*)&As[0][(mbase + fr) * KS + ks + fc + 8];
                ah[mb][3] = *(unsigned*)&As[0][(mbase + fr + 8) * KS + ks + fc + 8];
                al[mb][0] = *(unsigned*)&As[1][(mbase + fr) * KS + ks + fc];
                al[mb][1] = *(unsigned*)&As[1][(mbase + fr + 8) * KS + ks + fc];
                al[mb][2] = *(unsigned*)&As[1][(mbase + fr) * KS + ks + fc + 8];
                al[mb][3] = *(unsigned*)&As[1][(mbase + fr + 8) * KS + ks + fc + 8];
            }
#pragma unroll
            for (int nb = 0; nb < NBk; nb++) {
                int nbase = nw + nb * 8 + fr;
                unsigned bh0 = *(unsigned*)&Bs[0][nbase * KS + ks + fc];
                unsigned bh1 = *(unsigned*)&Bs[0][nbase * KS + ks + fc + 8];
                unsigned bl0 = *(unsigned*)&Bs[1][nbase * KS + ks + fc];
                unsigned bl1 = *(unsigned*)&Bs[1][nbase * KS + ks + fc + 8];
#pragma unroll
                for (int mb = 0; mb < MB; mb++) {
                    mma16816(acc[mb][nb], ah[mb], bh0, bh1);  // hi*hi
                    mma16816(acc[mb][nb], ah[mb], bl0, bl1);  // hi*lo
                    mma16816(acc[mb][nb], al[mb], bh0, bh1);  // lo*hi
                }
            }
        }
    }
    // epilogue
#pragma unroll
    for (int mb = 0; mb < MB; mb++)
#pragma unroll
        for (int nb = 0; nb < NBk; nb++) {
            float* cp = Cp + (long)(mw + mb * 16 + fr) * ldc + nw + nb * 8 + fc;
            *(float2*)cp = make_float2(acc[mb][nb][0], acc[mb][nb][1]);
            *(float2*)(cp + (long)8 * ldc) = make_float2(acc[mb][nb][2], acc[mb][nb][3]);
        }
}

// ---------------- softmax over j (in place), rows = (b,i,h) -----------------
__global__ __launch_bounds__(256) void softmax_kernel(float* __restrict__ s)
{
    int row = blockIdx.x * 8 + (threadIdx.x >> 5);
    int lane = threadIdx.x & 31;
    float* rp = s + (long)row * 1024;
    float4 v[8];
    float mx = -1e30f;
#pragma unroll
    for (int it = 0; it < 8; it++) {
        v[it] = ((const float4*)rp)[lane + it * 32];
        mx = fmaxf(mx, fmaxf(fmaxf(v[it].x, v[it].y), fmaxf(v[it].z, v[it].w)));
    }
#pragma unroll
    for (int o = 16; o > 0; o >>= 1) mx = fmaxf(mx, __shfl_xor_sync(0xffffffffu, mx, o));
    float sum = 0.f;
#pragma unroll
    for (int it = 0; it < 8; it++) {
        v[it].x = __expf(0.125f * (v[it].x - mx));
        v[it].y = __expf(0.125f * (v[it].y - mx));
        v[it].z = __expf(0.125f * (v[it].z - mx));
        v[it].w = __expf(0.125f * (v[it].w - mx));
        sum += v[it].x + v[it].y + v[it].z + v[it].w;
    }
#pragma unroll
    for (int o = 16; o > 0; o >>= 1) sum += __shfl_xor_sync(0xffffffffu, sum, o);
    float inv = 1.f / sum;
#pragma unroll
    for (int it = 0; it < 8; it++) {
        v[it].x *= inv; v[it].y *= inv; v[it].z *= inv; v[it].w *= inv;
        ((float4*)rp)[lane + it * 32] = v[it];
    }
}

// ---------------- talking heads mix + LayerNorm -> split bf16 ---------------
// reads probs g_s [b][i][h][j], writes w [b,g][i][j] as hi/lo bf16.
__global__ __launch_bounds__(256) void mixln_kernel(
    const float* __restrict__ s, const float* __restrict__ Wt,
    const float* __restrict__ gamma, const float* __restrict__ beta,
    bf16* __restrict__ whi, bf16* __restrict__ wlo)
{
    __shared__ float wts[16][17];
    __shared__ float gm[16], bt[16];
    int t = threadIdx.x;
    wts[t >> 4][t & 15] = Wt[t];
    if (t < 16) { gm[t] = gamma[t]; bt[t] = beta[t]; }
    __syncthreads();

    long gid = (long)blockIdx.x * 256 + t;        // 2M threads: (b,i) x j-pair
    int j2 = (int)(gid & 511);
    long bi = gid >> 9;                           // b*1024 + i
    const float* sp = s + bi * 16384 + j2 * 2;

    float sv0[16], sv1[16];
#pragma unroll
    for (int h = 0; h < 16; h++) {
        float2 v = *(const float2*)(sp + h * 1024);
        sv0[h] = v.x; sv1[h] = v.y;
    }
    float m0[16], m1[16], mu0 = 0.f, mu1 = 0.f;
#pragma unroll
    for (int g = 0; g < 16; g++) {
        float a = 0.f, b2 = 0.f;
#pragma unroll
        for (int h = 0; h < 16; h++) {
            a  = fmaf(sv0[h], wts[h][g], a);
            b2 = fmaf(sv1[h], wts[h][g], b2);
        }
        m0[g] = a; m1[g] = b2; mu0 += a; mu1 += b2;
    }
    mu0 *= (1.f / 16.f); mu1 *= (1.f / 16.f);
    float va0 = 0.f, va1 = 0.f;
#pragma unroll
    for (int g = 0; g < 16; g++) {
        float d0 = m0[g] - mu0, d1 = m1[g] - mu1;
        va0 = fmaf(d0, d0, va0); va1 = fmaf(d1, d1, va1);
    }
    float iv0 = rsqrtf(va0 * (1.f / 16.f) + LN_EPS);
    float iv1 = rsqrtf(va1 * (1.f / 16.f) + LN_EPS);
    long b = bi >> 10, i = bi & 1023;
#pragma unroll
    for (int g = 0; g < 16; g++) {
        float w0 = (m0[g] - mu0) * iv0 * gm[g] + bt[g];
        float w1 = (m1[g] - mu1) * iv1 * gm[g] + bt[g];
        bf16 h0 = __float2bfloat16(w0), h1 = __float2bfloat16(w1);
        bf162 ph; ph.x = h0; ph.y = h1;
        bf162 pl;
        pl.x = __float2bfloat16(w0 - __bfloat162float(h0));
        pl.y = __float2bfloat16(w1 - __bfloat162float(h1));
        long ob = ((b * 16 + g) << 20) + (i << 10) + j2 * 2;
        *(bf162*)(whi + ob) = ph;
        *(bf162*)(wlo + ob) = pl;
    }
}

// ---------------- driver -----------------------------------------------------
extern "C" void kernel_launch(void* const* d_in, const int* in_sizes, int n_in,
                              void* d_out, int out_size)
{
    const float* x     = (const float*)d_in[0];
    const float* ctx   = (const float*)d_in[1];
    const float* Wq    = (const float*)d_in[2];
    const float* Wkv   = (const float*)d_in[3];
    const float* Wt    = (const float*)d_in[4];
    const float* gamma = (const float*)d_in[5];
    const float* beta  = (const float*)d_in[6];
    float* out = (float*)d_out;

    bf16 *xhi, *xlo, *chi, *clo, *wqThi, *wqTlo, *wkThi, *wkTlo;
    bf16 *qhi, *qlo, *kvhi, *kvlo, *vThi, *vTlo, *whi, *wlo;
    float *qp, *kvp, *sp;
    cudaGetSymbolAddress((void**)&xhi, g_xhi);   cudaGetSymbolAddress((void**)&xlo, g_xlo);
    cudaGetSymbolAddress((void**)&chi, g_chi);   cudaGetSymbolAddress((void**)&clo, g_clo);
    cudaGetSymbolAddress((void**)&wqThi, g_wqThi); cudaGetSymbolAddress((void**)&wqTlo, g_wqTlo);
    cudaGetSymbolAddress((void**)&wkThi, g_wkThi); cudaGetSymbolAddress((void**)&wkTlo, g_wkTlo);
    cudaGetSymbolAddress((void**)&qhi, g_qhi);   cudaGetSymbolAddress((void**)&qlo, g_qlo);
    cudaGetSymbolAddress((void**)&kvhi, g_kvhi); cudaGetSymbolAddress((void**)&kvlo, g_kvlo);
    cudaGetSymbolAddress((void**)&vThi, g_vThi); cudaGetSymbolAddress((void**)&vTlo, g_vTlo);
    cudaGetSymbolAddress((void**)&whi, g_whi);   cudaGetSymbolAddress((void**)&wlo, g_wlo);
    cudaGetSymbolAddress((void**)&qp, g_q);
    cudaGetSymbolAddress((void**)&kvp, g_kv);
    cudaGetSymbolAddress((void**)&sp, g_s);

    // 1. splits of inputs
    split_kernel<<<4096, 256>>>(x, xhi, xlo, 4194304);
    split_kernel<<<4096, 256>>>(ctx, chi, clo, 4194304);
    tsplit_kernel<<<dim3(32, 32, 1), 256>>>(Wq, 0, 1024, wqThi, wqTlo, 0, 1024);
    tsplit_kernel<<<dim3(64, 32, 1), 256>>>(Wkv, 0, 2048, wkThi, wkTlo, 0, 1024);

    // 2. projections: q = x@Wq, kv = ctx@Wkv
    gemm_bf16<128, 128, 64, 32><<<dim3(8, 32, 1), 256>>>(
        xhi, xlo, wqThi, wqTlo, qp, 1024, 1024, 1024, 1024,
        1, 0, 0, 0, 0, 0, 0);
    gemm_bf16<128, 128, 64, 32><<<dim3(16, 32, 1), 256>>>(
        chi, clo, wkThi, wkTlo, kvp, 1024, 1024, 1024, 2048,
        1, 0, 0, 0, 0, 0, 0);

    // 3. splits of q, kv; transposed split of v per batch
    split_kernel<<<4096, 256>>>(qp, qhi, qlo, 4194304);
    split_kernel<<<8192, 256>>>(kvp, kvhi, kvlo, 8388608);
    tsplit_kernel<<<dim3(32, 32, 4), 256>>>(kvp + 1024, 2097152, 2048, vThi, vTlo, 1048576, 1024);

    // 4. raw scores per (b,h): S = Q_h K_h^T -> g_s [b][i][h][j]
    gemm_bf16<128, 128, 64, 32><<<dim3(8, 8, 64), 256>>>(
        qhi, qlo, kvhi, kvlo, sp, 64, 1024, 2048, 16384,
        16, 1048576, 64, 2097152, 64, 16777216, 1024);

    // 5. softmax rows (b,i,h)
    softmax_kernel<<<8192, 256>>>(sp);

    // 6. talking-heads mix + LN -> split bf16 w [b,g][i][j]
    mixln_kernel<<<8192, 256>>>(sp, Wt, gamma, beta, whi, wlo);

    // 7. AV per (b,g): out[i][g*64+d] = sum_j w[i][j] v[j][d]
    gemm_bf16<128, 64, 32, 32><<<dim3(1, 8, 64), 256>>>(
        whi, wlo, vThi, vTlo, out, 1024, 1024, 1024, 1024,
        16, 16777216, 1048576, 1048576, 65536, 1048576, 64);
}